// round 4
// baseline (speedup 1.0000x reference)
#include <cuda_runtime.h>
#include <cuda_bf16.h>
#include <math.h>

// ---------------------------------------------------------------------------
// MS Deformable Attention — fp32 baseline
// query[8,1024,256], ref[8,1024,4,2], value[8,13294,256],
// so_w[256,256] so_b[256], aw_w[256,128] aw_b[128],
// vp_w[256,256] vp_b[256], op_w[256,256] op_b[256] -> out[8,1024,256]
// ---------------------------------------------------------------------------

#define BS        8
#define LEN_Q     1024
#define EMBED     256
#define NHEAD     8
#define NLVL      4
#define NPTS      4
#define HEADDIM   32
#define LEN_V     13294
#define NQ_TOT    (BS * LEN_Q)          // 8192
#define MV_TOT    (BS * LEN_V)          // 106352
#define TPQ       (NHEAD * NLVL * NPTS) // 128

// Level geometry (compile-time)
__device__ __constant__ int c_lvl_start[4] = {0, 10000, 12500, 13125};
__device__ __constant__ int c_lvl_hw[4]    = {100, 50, 25, 13};   // H == W per level

// Scratch (static device globals — allocation-guard safe)
__device__ float g_vproj[(size_t)MV_TOT * EMBED];   // ~108.9 MB
__device__ float g_locx[NQ_TOT * TPQ];
__device__ float g_locy[NQ_TOT * TPQ];
__device__ float g_wgt [NQ_TOT * TPQ];
__device__ float g_att [NQ_TOT * EMBED];

// ---------------------------------------------------------------------------
// Generic fp32 GEMM + bias: C[M,N] = A[M,K] @ B[K,N] + bias[N]
// BM=BN=64, BK=16, 256 threads, 4x4 micro-tile per thread.
// Requires N % 64 == 0, K % 16 == 0 (true here: N=256, K=256). M guarded.
// ---------------------------------------------------------------------------
__global__ __launch_bounds__(256) void gemm_bias_kernel(
    const float* __restrict__ A, const float* __restrict__ B,
    const float* __restrict__ bias, float* __restrict__ C,
    int M, int N, int K)
{
    __shared__ float As[16][64];   // [k][m]
    __shared__ float Bs[16][64];   // [k][n]

    const int tid = threadIdx.x;
    const int tx  = tid & 15;      // n-tile coordinate
    const int ty  = tid >> 4;      // m-tile coordinate
    const int m0  = blockIdx.y * 64;
    const int n0  = blockIdx.x * 64;

    // A-tile load mapping: 64 rows x 16 cols, each thread one float4
    const int arow = tid >> 2;          // 0..63
    const int ac4  = (tid & 3) * 4;     // 0,4,8,12
    const bool aval = (m0 + arow) < M;
    const float* aptr = A + (size_t)(m0 + arow) * K + ac4;
    // B-tile load mapping: 16 rows x 64 cols, each thread one float4
    const int brow = tid >> 4;          // 0..15
    const int bc4  = (tid & 15) * 4;    // 0..60
    const float* bptr = B + (size_t)brow * N + n0 + bc4;

    float acc[4][4] = {};

    for (int k0 = 0; k0 < K; k0 += 16) {
        float4 av = aval ? *(const float4*)(aptr + k0) : make_float4(0.f, 0.f, 0.f, 0.f);
        float4 bv = *(const float4*)(bptr + (size_t)k0 * N);
        __syncthreads();
        As[ac4 + 0][arow] = av.x;
        As[ac4 + 1][arow] = av.y;
        As[ac4 + 2][arow] = av.z;
        As[ac4 + 3][arow] = av.w;
        *(float4*)&Bs[brow][bc4] = bv;
        __syncthreads();

#pragma unroll
        for (int kk = 0; kk < 16; kk++) {
            float4 ra = *(const float4*)&As[kk][ty * 4];
            float4 rb = *(const float4*)&Bs[kk][tx * 4];
            float a0 = ra.x, a1 = ra.y, a2 = ra.z, a3 = ra.w;
            float b0 = rb.x, b1 = rb.y, b2 = rb.z, b3 = rb.w;
            acc[0][0] += a0 * b0; acc[0][1] += a0 * b1; acc[0][2] += a0 * b2; acc[0][3] += a0 * b3;
            acc[1][0] += a1 * b0; acc[1][1] += a1 * b1; acc[1][2] += a1 * b2; acc[1][3] += a1 * b3;
            acc[2][0] += a2 * b0; acc[2][1] += a2 * b1; acc[2][2] += a2 * b2; acc[2][3] += a2 * b3;
            acc[3][0] += a3 * b0; acc[3][1] += a3 * b1; acc[3][2] += a3 * b2; acc[3][3] += a3 * b3;
        }
    }

    const int gc = n0 + tx * 4;
    float4 bb = *(const float4*)&bias[gc];
#pragma unroll
    for (int i = 0; i < 4; i++) {
        int gr = m0 + ty * 4 + i;
        if (gr < M) {
            float4 o;
            o.x = acc[i][0] + bb.x;
            o.y = acc[i][1] + bb.y;
            o.z = acc[i][2] + bb.z;
            o.w = acc[i][3] + bb.w;
            *(float4*)&C[(size_t)gr * N + gc] = o;
        }
    }
}

// ---------------------------------------------------------------------------
// Fused: so = q@so_w+so_b ; aw = softmax(q@aw_w+aw_b) per head over 16 ;
// loc -> pixel coords. QB queries per block, 256 threads.
// Thread j computes column j of so (j<256) and of aw (j<128).
// ---------------------------------------------------------------------------
#define QB 8
__global__ __launch_bounds__(256) void samp_prep_kernel(
    const float* __restrict__ q, const float* __restrict__ ref,
    const float* __restrict__ so_w, const float* __restrict__ so_b,
    const float* __restrict__ aw_w, const float* __restrict__ aw_b)
{
    __shared__ float qs[QB][EMBED];
    __shared__ float sos[QB][EMBED];
    __shared__ float aws[QB][TPQ];

    const int tid = threadIdx.x;
    const int bq0 = blockIdx.x * QB;

    for (int i = tid; i < QB * EMBED; i += 256)
        qs[i >> 8][i & 255] = q[(size_t)(bq0 + (i >> 8)) * EMBED + (i & 255)];
    __syncthreads();

    const int j = tid;
    float accS[QB] = {};
    float accA[QB] = {};
    const bool hasA = (j < TPQ);
#pragma unroll 4
    for (int k = 0; k < EMBED; k++) {
        float w1 = so_w[k * EMBED + j];
        float w2 = hasA ? aw_w[k * TPQ + j] : 0.f;
#pragma unroll
        for (int qq = 0; qq < QB; qq++) {
            float s = qs[qq][k];
            accS[qq] = fmaf(s, w1, accS[qq]);
            accA[qq] = fmaf(s, w2, accA[qq]);
        }
    }
    float bS = so_b[j];
    float bA = hasA ? aw_b[j] : 0.f;
#pragma unroll
    for (int qq = 0; qq < QB; qq++) {
        sos[qq][j] = accS[qq] + bS;
        if (hasA) aws[qq][j] = accA[qq] + bA;
    }
    __syncthreads();

    // softmax over 16 per (query, head): 64 work items
    if (tid < QB * NHEAD) {
        int qq = tid >> 3, h = tid & 7;
        float* a = &aws[qq][h * 16];
        float m = a[0];
#pragma unroll
        for (int i = 1; i < 16; i++) m = fmaxf(m, a[i]);
        float s = 0.f;
#pragma unroll
        for (int i = 0; i < 16; i++) { float e = __expf(a[i] - m); a[i] = e; s += e; }
        float inv = 1.f / s;
#pragma unroll
        for (int i = 0; i < 16; i++) a[i] *= inv;
    }
    __syncthreads();

    // locations: QB*128 items. t enumerates (h,l,p); so index 2t, 2t+1.
    for (int it = tid; it < QB * TPQ; it += 256) {
        int qq = it >> 7;
        int t  = it & 127;
        int l  = (t >> 2) & 3;
        int bq = bq0 + qq;
        float rx = ref[((size_t)bq * NLVL + l) * 2 + 0];
        float ry = ref[((size_t)bq * NLVL + l) * 2 + 1];
        float sx = sos[qq][t * 2 + 0];
        float sy = sos[qq][t * 2 + 1];
        float wh = (float)c_lvl_hw[l];          // W == H
        float lx = rx + sx / wh;
        float ly = ry + sy / wh;
        size_t o = (size_t)bq * TPQ + t;
        g_locx[o] = lx * wh - 0.5f;             // pixel x
        g_locy[o] = ly * wh - 0.5f;             // pixel y
        g_wgt[o]  = aws[qq][t];
    }
}

// ---------------------------------------------------------------------------
// Sampling: block = (b,q); warp = head; lane = channel within head.
// Each corner gather: 32 contiguous floats -> one coalesced 128B transaction.
// ---------------------------------------------------------------------------
__global__ __launch_bounds__(256) void sample_kernel()
{
    const int bq   = blockIdx.x;          // 0..8191
    const int h    = threadIdx.x >> 5;    // head
    const int lane = threadIdx.x & 31;    // channel
    const int b    = bq >> 10;

    const float* vb = g_vproj + (size_t)b * LEN_V * EMBED;
    const int ch = h * HEADDIM + lane;
    const int base = bq * TPQ + h * 16;

    float acc = 0.f;
#pragma unroll
    for (int l = 0; l < NLVL; l++) {
        const int HW = c_lvl_hw[l];
        const float* vl = vb + (size_t)c_lvl_start[l] * EMBED;
#pragma unroll
        for (int p = 0; p < NPTS; p++) {
            int i = base + l * 4 + p;
            float x = g_locx[i], y = g_locy[i], wg = g_wgt[i];
            float x0f = floorf(x), y0f = floorf(y);
            int ix0 = (int)x0f, iy0 = (int)y0f;
            int ix1 = ix0 + 1, iy1 = iy0 + 1;
            float fx = x - x0f, fy = y - y0f;
            bool vx0 = (ix0 >= 0) & (ix0 < HW);
            bool vx1 = (ix1 >= 0) & (ix1 < HW);
            bool vy0 = (iy0 >= 0) & (iy0 < HW);
            bool vy1 = (iy1 >= 0) & (iy1 < HW);

            float v00 = (vx0 & vy0) ? vl[((size_t)(iy0 * HW + ix0)) * EMBED + ch] : 0.f;
            float v01 = (vx1 & vy0) ? vl[((size_t)(iy0 * HW + ix1)) * EMBED + ch] : 0.f;
            float v10 = (vx0 & vy1) ? vl[((size_t)(iy1 * HW + ix0)) * EMBED + ch] : 0.f;
            float v11 = (vx1 & vy1) ? vl[((size_t)(iy1 * HW + ix1)) * EMBED + ch] : 0.f;

            float top = fmaf(fx, v01 - v00, v00);   // (1-fx)*v00 + fx*v01
            float bot = fmaf(fx, v11 - v10, v10);
            float smp = fmaf(fy, bot - top, top);
            acc = fmaf(wg, smp, acc);
        }
    }
    g_att[(size_t)bq * EMBED + ch] = acc;
}

// ---------------------------------------------------------------------------
// Launch
// Input order: query, reference_points, value, value_spatial_shapes(ignored),
//              so_w, so_b, aw_w, aw_b, vp_w, vp_b, op_w, op_b
// ---------------------------------------------------------------------------
extern "C" void kernel_launch(void* const* d_in, const int* in_sizes, int n_in,
                              void* d_out, int out_size)
{
    const float* query = (const float*)d_in[0];
    const float* refp  = (const float*)d_in[1];
    const float* value = (const float*)d_in[2];
    // d_in[3] = value_spatial_shapes (compile-time constant, ignored)
    const float* so_w = (const float*)d_in[4];
    const float* so_b = (const float*)d_in[5];
    const float* aw_w = (const float*)d_in[6];
    const float* aw_b = (const float*)d_in[7];
    const float* vp_w = (const float*)d_in[8];
    const float* vp_b = (const float*)d_in[9];
    const float* op_w = (const float*)d_in[10];
    const float* op_b = (const float*)d_in[11];
    float* out = (float*)d_out;

    float *vproj_ptr, *att_ptr;
    cudaGetSymbolAddress((void**)&vproj_ptr, g_vproj);
    cudaGetSymbolAddress((void**)&att_ptr,  g_att);

    // 1) v projection: [MV_TOT,256] @ [256,256] + vp_b
    {
        dim3 grid(EMBED / 64, (MV_TOT + 63) / 64);
        gemm_bias_kernel<<<grid, 256>>>(value, vp_w, vp_b, vproj_ptr,
                                        MV_TOT, EMBED, EMBED);
    }
    // 2) sampling offsets / weights / locations
    {
        samp_prep_kernel<<<NQ_TOT / QB, 256>>>(query, refp, so_w, so_b, aw_w, aw_b);
    }
    // 3) bilinear sampling + weighted accumulation
    {
        sample_kernel<<<NQ_TOT, 256>>>();
    }
    // 4) output projection: [8192,256] @ [256,256] + op_b
    {
        dim3 grid(EMBED / 64, NQ_TOT / 64);
        gemm_bias_kernel<<<grid, 256>>>(att_ptr, op_w, op_b, out,
                                        NQ_TOT, EMBED, EMBED);
    }
}

// round 5
// speedup vs baseline: 1.7754x; 1.7754x over previous
#include <cuda_runtime.h>
#include <cuda_bf16.h>
#include <math.h>

// ---------------------------------------------------------------------------
// MS Deformable Attention
// query[8,1024,256], ref[8,1024,4,2], value[8,13294,256],
// so_w[256,256] so_b[256], aw_w[256,128] aw_b[128],
// vp_w[256,256] vp_b[256], op_w[256,256] op_b[256] -> out[8,1024,256]
// v-projection now runs on the tensor pipe (mma.sync tf32).
// ---------------------------------------------------------------------------

#define BS        8
#define LEN_Q     1024
#define EMBED     256
#define NHEAD     8
#define NLVL      4
#define NPTS      4
#define HEADDIM   32
#define LEN_V     13294
#define NQ_TOT    (BS * LEN_Q)          // 8192
#define MV_TOT    (BS * LEN_V)          // 106352
#define TPQ       (NHEAD * NLVL * NPTS) // 128

__device__ __constant__ int c_lvl_start[4] = {0, 10000, 12500, 13125};
__device__ __constant__ int c_lvl_hw[4]    = {100, 50, 25, 13};

__device__ float g_vproj[(size_t)MV_TOT * EMBED];   // ~108.9 MB
__device__ float g_locx[NQ_TOT * TPQ];
__device__ float g_locy[NQ_TOT * TPQ];
__device__ float g_wgt [NQ_TOT * TPQ];
__device__ float g_att [NQ_TOT * EMBED];

// ---------------------------------------------------------------------------
// tf32 helpers
// ---------------------------------------------------------------------------
__device__ __forceinline__ float f2tf(float x) {
    unsigned u;
    asm("cvt.rna.tf32.f32 %0, %1;" : "=r"(u) : "f"(x));
    return __uint_as_float(u);
}

__device__ __forceinline__ void mma_tf32(float c[4], const unsigned a[4], const unsigned b[2]) {
    asm volatile(
        "mma.sync.aligned.m16n8k8.row.col.f32.tf32.tf32.f32 "
        "{%0,%1,%2,%3}, {%4,%5,%6,%7}, {%8,%9}, {%0,%1,%2,%3};"
        : "+f"(c[0]), "+f"(c[1]), "+f"(c[2]), "+f"(c[3])
        : "r"(a[0]), "r"(a[1]), "r"(a[2]), "r"(a[3]), "r"(b[0]), "r"(b[1]));
}

// ---------------------------------------------------------------------------
// tf32 tensor-core GEMM + bias: C[M,256] = A[M,256] @ B[256,256] + bias
// BM=128, BN=128, BK=16. 256 threads = 8 warps (2x4), warp tile 64x32.
// mma.sync.m16n8k8.tf32, fp32 accumulate. Double-buffered SMEM.
// Padding: As stride 20, Bs stride 132 -> conflict-free fragment loads.
// ---------------------------------------------------------------------------
#define GK 256
#define GN 256
__global__ __launch_bounds__(256) void gemm_tf32_kernel(
    const float* __restrict__ A, const float* __restrict__ B,
    const float* __restrict__ bias, float* __restrict__ C, int M)
{
    __shared__ float As[2][128][20];   // [m][k], stride 20 (== 4 mod 32)
    __shared__ float Bs[2][16][132];   // [k][n], stride 132 (== 4 mod 32)

    const int tid  = threadIdx.x;
    const int w    = tid >> 5;
    const int lane = tid & 31;
    const int wm   = (w >> 2) * 64;    // warp row offset (0 or 64)
    const int wn   = (w & 3) * 32;     // warp col offset (0,32,64,96)
    const int tr   = lane >> 2;        // 0..7
    const int tc   = lane & 3;         // 0..3
    const int m0   = blockIdx.y * 128;
    const int n0   = blockIdx.x * 128;

    // gmem staging registers
    float4 ra[2], rb[2];

    // A tile load: 128 rows x 16 cols = 512 float4; 2 per thread.
    // lin = tid + i*256 : row = lin>>2, col = (lin&3)*4
    // B tile load: 16 rows x 128 cols : row = lin>>5, col = (lin&31)*4
    auto load_gmem = [&](int k0) {
#pragma unroll
        for (int i = 0; i < 2; i++) {
            int lin = tid + i * 256;
            int arow = lin >> 2, acol = (lin & 3) * 4;
            if (m0 + arow < M)
                ra[i] = *(const float4*)&A[(size_t)(m0 + arow) * GK + k0 + acol];
            else
                ra[i] = make_float4(0.f, 0.f, 0.f, 0.f);
            int brow = lin >> 5, bcol = (lin & 31) * 4;
            rb[i] = *(const float4*)&B[(size_t)(k0 + brow) * GN + n0 + bcol];
        }
    };

    auto store_smem = [&](int buf) {
#pragma unroll
        for (int i = 0; i < 2; i++) {
            int lin = tid + i * 256;
            int arow = lin >> 2, acol = (lin & 3) * 4;
            float4 va;
            va.x = f2tf(ra[i].x); va.y = f2tf(ra[i].y);
            va.z = f2tf(ra[i].z); va.w = f2tf(ra[i].w);
            *(float4*)&As[buf][arow][acol] = va;
            int brow = lin >> 5, bcol = (lin & 31) * 4;
            float4 vb;
            vb.x = f2tf(rb[i].x); vb.y = f2tf(rb[i].y);
            vb.z = f2tf(rb[i].z); vb.w = f2tf(rb[i].w);
            *(float4*)&Bs[buf][brow][bcol] = vb;
        }
    };

    float acc[4][4][4] = {};   // [mi][ni][creg]

    auto compute = [&](int buf) {
#pragma unroll
        for (int kk = 0; kk < 2; kk++) {
            unsigned af[4][4], bf[4][2];
#pragma unroll
            for (int mi = 0; mi < 4; mi++) {
                int mr = wm + mi * 16 + tr;
                int kc = kk * 8 + tc;
                af[mi][0] = __float_as_uint(As[buf][mr    ][kc    ]);
                af[mi][1] = __float_as_uint(As[buf][mr + 8][kc    ]);
                af[mi][2] = __float_as_uint(As[buf][mr    ][kc + 4]);
                af[mi][3] = __float_as_uint(As[buf][mr + 8][kc + 4]);
            }
#pragma unroll
            for (int ni = 0; ni < 4; ni++) {
                int nc = wn + ni * 8 + tr;
                bf[ni][0] = __float_as_uint(Bs[buf][kk * 8 + tc    ][nc]);
                bf[ni][1] = __float_as_uint(Bs[buf][kk * 8 + tc + 4][nc]);
            }
#pragma unroll
            for (int mi = 0; mi < 4; mi++)
#pragma unroll
                for (int ni = 0; ni < 4; ni++)
                    mma_tf32(acc[mi][ni], af[mi], bf[ni]);
        }
    };

    // --- main loop, double buffered ---
    int buf = 0;
    load_gmem(0);
    store_smem(0);
    __syncthreads();
#pragma unroll 1
    for (int k0 = 16; k0 < GK; k0 += 16) {
        load_gmem(k0);
        compute(buf);
        store_smem(buf ^ 1);
        __syncthreads();
        buf ^= 1;
    }
    compute(buf);

    // --- epilogue ---
#pragma unroll
    for (int mi = 0; mi < 4; mi++) {
        int r0 = m0 + wm + mi * 16 + tr;
#pragma unroll
        for (int ni = 0; ni < 4; ni++) {
            int col = n0 + wn + ni * 8 + tc * 2;
            float bx = bias[col], by = bias[col + 1];
            if (r0 < M) {
                float2 o0 = make_float2(acc[mi][ni][0] + bx, acc[mi][ni][1] + by);
                *(float2*)&C[(size_t)r0 * GN + col] = o0;
            }
            if (r0 + 8 < M) {
                float2 o1 = make_float2(acc[mi][ni][2] + bx, acc[mi][ni][3] + by);
                *(float2*)&C[(size_t)(r0 + 8) * GN + col] = o1;
            }
        }
    }
}

// ---------------------------------------------------------------------------
// fp32 GEMM + bias (kept for the small output projection)
// ---------------------------------------------------------------------------
__global__ __launch_bounds__(256) void gemm_bias_kernel(
    const float* __restrict__ A, const float* __restrict__ B,
    const float* __restrict__ bias, float* __restrict__ C,
    int M, int N, int K)
{
    __shared__ float As[16][64];
    __shared__ float Bs[16][64];

    const int tid = threadIdx.x;
    const int tx  = tid & 15;
    const int ty  = tid >> 4;
    const int m0  = blockIdx.y * 64;
    const int n0  = blockIdx.x * 64;

    const int arow = tid >> 2;
    const int ac4  = (tid & 3) * 4;
    const bool aval = (m0 + arow) < M;
    const float* aptr = A + (size_t)(m0 + arow) * K + ac4;
    const int brow = tid >> 4;
    const int bc4  = (tid & 15) * 4;
    const float* bptr = B + (size_t)brow * N + n0 + bc4;

    float acc[4][4] = {};

    for (int k0 = 0; k0 < K; k0 += 16) {
        float4 av = aval ? *(const float4*)(aptr + k0) : make_float4(0.f, 0.f, 0.f, 0.f);
        float4 bv = *(const float4*)(bptr + (size_t)k0 * N);
        __syncthreads();
        As[ac4 + 0][arow] = av.x;
        As[ac4 + 1][arow] = av.y;
        As[ac4 + 2][arow] = av.z;
        As[ac4 + 3][arow] = av.w;
        *(float4*)&Bs[brow][bc4] = bv;
        __syncthreads();

#pragma unroll
        for (int kk = 0; kk < 16; kk++) {
            float4 ra = *(const float4*)&As[kk][ty * 4];
            float4 rb = *(const float4*)&Bs[kk][tx * 4];
            float a0 = ra.x, a1 = ra.y, a2 = ra.z, a3 = ra.w;
            float b0 = rb.x, b1 = rb.y, b2 = rb.z, b3 = rb.w;
            acc[0][0] += a0 * b0; acc[0][1] += a0 * b1; acc[0][2] += a0 * b2; acc[0][3] += a0 * b3;
            acc[1][0] += a1 * b0; acc[1][1] += a1 * b1; acc[1][2] += a1 * b2; acc[1][3] += a1 * b3;
            acc[2][0] += a2 * b0; acc[2][1] += a2 * b1; acc[2][2] += a2 * b2; acc[2][3] += a2 * b3;
            acc[3][0] += a3 * b0; acc[3][1] += a3 * b1; acc[3][2] += a3 * b2; acc[3][3] += a3 * b3;
        }
    }

    const int gc = n0 + tx * 4;
    float4 bb = *(const float4*)&bias[gc];
#pragma unroll
    for (int i = 0; i < 4; i++) {
        int gr = m0 + ty * 4 + i;
        if (gr < M) {
            float4 o;
            o.x = acc[i][0] + bb.x;
            o.y = acc[i][1] + bb.y;
            o.z = acc[i][2] + bb.z;
            o.w = acc[i][3] + bb.w;
            *(float4*)&C[(size_t)gr * N + gc] = o;
        }
    }
}

// ---------------------------------------------------------------------------
// Fused so/aw projections + softmax + location prep (unchanged)
// ---------------------------------------------------------------------------
#define QB 8
__global__ __launch_bounds__(256) void samp_prep_kernel(
    const float* __restrict__ q, const float* __restrict__ ref,
    const float* __restrict__ so_w, const float* __restrict__ so_b,
    const float* __restrict__ aw_w, const float* __restrict__ aw_b)
{
    __shared__ float qs[QB][EMBED];
    __shared__ float sos[QB][EMBED];
    __shared__ float aws[QB][TPQ];

    const int tid = threadIdx.x;
    const int bq0 = blockIdx.x * QB;

    for (int i = tid; i < QB * EMBED; i += 256)
        qs[i >> 8][i & 255] = q[(size_t)(bq0 + (i >> 8)) * EMBED + (i & 255)];
    __syncthreads();

    const int j = tid;
    float accS[QB] = {};
    float accA[QB] = {};
    const bool hasA = (j < TPQ);
#pragma unroll 4
    for (int k = 0; k < EMBED; k++) {
        float w1 = so_w[k * EMBED + j];
        float w2 = hasA ? aw_w[k * TPQ + j] : 0.f;
#pragma unroll
        for (int qq = 0; qq < QB; qq++) {
            float s = qs[qq][k];
            accS[qq] = fmaf(s, w1, accS[qq]);
            accA[qq] = fmaf(s, w2, accA[qq]);
        }
    }
    float bS = so_b[j];
    float bA = hasA ? aw_b[j] : 0.f;
#pragma unroll
    for (int qq = 0; qq < QB; qq++) {
        sos[qq][j] = accS[qq] + bS;
        if (hasA) aws[qq][j] = accA[qq] + bA;
    }
    __syncthreads();

    if (tid < QB * NHEAD) {
        int qq = tid >> 3, h = tid & 7;
        float* a = &aws[qq][h * 16];
        float m = a[0];
#pragma unroll
        for (int i = 1; i < 16; i++) m = fmaxf(m, a[i]);
        float s = 0.f;
#pragma unroll
        for (int i = 0; i < 16; i++) { float e = __expf(a[i] - m); a[i] = e; s += e; }
        float inv = 1.f / s;
#pragma unroll
        for (int i = 0; i < 16; i++) a[i] *= inv;
    }
    __syncthreads();

    for (int it = tid; it < QB * TPQ; it += 256) {
        int qq = it >> 7;
        int t  = it & 127;
        int l  = (t >> 2) & 3;
        int bq = bq0 + qq;
        float rx = ref[((size_t)bq * NLVL + l) * 2 + 0];
        float ry = ref[((size_t)bq * NLVL + l) * 2 + 1];
        float sx = sos[qq][t * 2 + 0];
        float sy = sos[qq][t * 2 + 1];
        float wh = (float)c_lvl_hw[l];
        float lx = rx + sx / wh;
        float ly = ry + sy / wh;
        size_t o = (size_t)bq * TPQ + t;
        g_locx[o] = lx * wh - 0.5f;
        g_locy[o] = ly * wh - 0.5f;
        g_wgt[o]  = aws[qq][t];
    }
}

// ---------------------------------------------------------------------------
// Bilinear sampling + weighted accumulation (unchanged)
// ---------------------------------------------------------------------------
__global__ __launch_bounds__(256) void sample_kernel()
{
    const int bq   = blockIdx.x;
    const int h    = threadIdx.x >> 5;
    const int lane = threadIdx.x & 31;
    const int b    = bq >> 10;

    const float* vb = g_vproj + (size_t)b * LEN_V * EMBED;
    const int ch = h * HEADDIM + lane;
    const int base = bq * TPQ + h * 16;

    float acc = 0.f;
#pragma unroll
    for (int l = 0; l < NLVL; l++) {
        const int HW = c_lvl_hw[l];
        const float* vl = vb + (size_t)c_lvl_start[l] * EMBED;
#pragma unroll
        for (int p = 0; p < NPTS; p++) {
            int i = base + l * 4 + p;
            float x = g_locx[i], y = g_locy[i], wg = g_wgt[i];
            float x0f = floorf(x), y0f = floorf(y);
            int ix0 = (int)x0f, iy0 = (int)y0f;
            int ix1 = ix0 + 1, iy1 = iy0 + 1;
            float fx = x - x0f, fy = y - y0f;
            bool vx0 = (ix0 >= 0) & (ix0 < HW);
            bool vx1 = (ix1 >= 0) & (ix1 < HW);
            bool vy0 = (iy0 >= 0) & (iy0 < HW);
            bool vy1 = (iy1 >= 0) & (iy1 < HW);

            float v00 = (vx0 & vy0) ? vl[((size_t)(iy0 * HW + ix0)) * EMBED + ch] : 0.f;
            float v01 = (vx1 & vy0) ? vl[((size_t)(iy0 * HW + ix1)) * EMBED + ch] : 0.f;
            float v10 = (vx0 & vy1) ? vl[((size_t)(iy1 * HW + ix0)) * EMBED + ch] : 0.f;
            float v11 = (vx1 & vy1) ? vl[((size_t)(iy1 * HW + ix1)) * EMBED + ch] : 0.f;

            float top = fmaf(fx, v01 - v00, v00);
            float bot = fmaf(fx, v11 - v10, v10);
            float smp = fmaf(fy, bot - top, top);
            acc = fmaf(wg, smp, acc);
        }
    }
    g_att[(size_t)bq * EMBED + ch] = acc;
}

// ---------------------------------------------------------------------------
// Launch
// ---------------------------------------------------------------------------
extern "C" void kernel_launch(void* const* d_in, const int* in_sizes, int n_in,
                              void* d_out, int out_size)
{
    const float* query = (const float*)d_in[0];
    const float* refp  = (const float*)d_in[1];
    const float* value = (const float*)d_in[2];
    const float* so_w = (const float*)d_in[4];
    const float* so_b = (const float*)d_in[5];
    const float* aw_w = (const float*)d_in[6];
    const float* aw_b = (const float*)d_in[7];
    const float* vp_w = (const float*)d_in[8];
    const float* vp_b = (const float*)d_in[9];
    const float* op_w = (const float*)d_in[10];
    const float* op_b = (const float*)d_in[11];
    float* out = (float*)d_out;

    float *vproj_ptr, *att_ptr;
    cudaGetSymbolAddress((void**)&vproj_ptr, g_vproj);
    cudaGetSymbolAddress((void**)&att_ptr,  g_att);

    // 1) v projection on the tensor pipe: [106352,256] @ [256,256] + vp_b
    {
        dim3 grid(EMBED / 128, (MV_TOT + 127) / 128);   // (2, 831)
        gemm_tf32_kernel<<<grid, 256>>>(value, vp_w, vp_b, vproj_ptr, MV_TOT);
    }
    // 2) sampling offsets / weights / locations
    samp_prep_kernel<<<NQ_TOT / QB, 256>>>(query, refp, so_w, so_b, aw_w, aw_b);
    // 3) bilinear sampling + weighted accumulation
    sample_kernel<<<NQ_TOT, 256>>>();
    // 4) output projection (fp32, small): [8192,256] @ [256,256] + op_b
    {
        dim3 grid(EMBED / 64, NQ_TOT / 64);
        gemm_bias_kernel<<<grid, 256>>>(att_ptr, op_w, op_b, out, NQ_TOT, EMBED, EMBED);
    }
}